// round 12
// baseline (speedup 1.0000x reference)
#include <cuda_runtime.h>
#include <math.h>
#include <stdint.h>

#define NB 8
#define NT 2048
#define NC 1024
#define NH 64
#define QSCALE 0.125f     // 64^-0.5
#define NQT 16            // query tiles of 128 rows per batch
#define NITEMS (NB * 40)  // 320 work items

// Scratch for projections.
__device__ float g_q[NB * NT * NH];
__device__ float g_k[NB * NT * NH];
__device__ float g_v[NB * NT * NH];

// Split-KV partials: slot = (b*16 + it)*4 + piece  (512 slots x 128 rows)
__device__ float g_po[512 * 128 * NH];
__device__ float g_pm[512 * 128];
__device__ float g_pl[512 * 128];
__device__ int   g_items[NITEMS * 4];   // b*16+it, kv0, kv1, piece
__device__ int   g_counter;

// ---------------------------------------------------------------------------
// Fused projection GEMM (proven R4 version): {q,k,v} = x @ {wq,wk,wv}
// ---------------------------------------------------------------------------
#define PBK 16
#define PAP 132
#define PBP 196

__global__ __launch_bounds__(256) void proj_kernel(
    const float* __restrict__ x,
    const float* __restrict__ wq,
    const float* __restrict__ wk,
    const float* __restrict__ wv)
{
    __shared__ float sA[2][PBK][PAP];
    __shared__ float sB[2][PBK][PBP];

    const int m0  = blockIdx.x * 128;
    const int tid = threadIdx.x;
    const int tr  = tid >> 4;
    const int tc  = tid & 15;

    const float* wsel[3] = {wq, wk, wv};
    float*       dsel[3] = {g_q, g_k, g_v};

    float acc[8][12];
    #pragma unroll
    for (int i = 0; i < 8; i++)
        #pragma unroll
        for (int j = 0; j < 12; j++) acc[i][j] = 0.f;

    float4 ar[2], br[3];
    #pragma unroll
    for (int u = 0; u < 2; u++) {
        int f = tid * 2 + u;
        int r = f >> 2, c4 = f & 3;
        ar[u] = *(const float4*)&x[(size_t)(m0 + r) * NC + c4 * 4];
    }
    #pragma unroll
    for (int u = 0; u < 3; u++) {
        int f  = tid * 3 + u;
        int kk = f / 48, c4 = f % 48;
        int col = c4 * 4;
        br[u] = *(const float4*)&wsel[col >> 6][(size_t)kk * NH + (col & 63)];
    }
    #pragma unroll
    for (int u = 0; u < 2; u++) {
        int f = tid * 2 + u;
        int r = f >> 2, c4 = f & 3;
        sA[0][c4 * 4 + 0][r] = ar[u].x;
        sA[0][c4 * 4 + 1][r] = ar[u].y;
        sA[0][c4 * 4 + 2][r] = ar[u].z;
        sA[0][c4 * 4 + 3][r] = ar[u].w;
    }
    #pragma unroll
    for (int u = 0; u < 3; u++) {
        int f  = tid * 3 + u;
        int kk = f / 48, c4 = f % 48;
        *(float4*)&sB[0][kk][c4 * 4] = br[u];
    }
    __syncthreads();

    const int NSTEP = NC / PBK;
    for (int ks = 0; ks < NSTEP; ks++) {
        int cur = ks & 1;
        if (ks + 1 < NSTEP) {
            int k0 = (ks + 1) * PBK;
            #pragma unroll
            for (int u = 0; u < 2; u++) {
                int f = tid * 2 + u;
                int r = f >> 2, c4 = f & 3;
                ar[u] = *(const float4*)&x[(size_t)(m0 + r) * NC + k0 + c4 * 4];
            }
            #pragma unroll
            for (int u = 0; u < 3; u++) {
                int f  = tid * 3 + u;
                int kk = f / 48, c4 = f % 48;
                int col = c4 * 4;
                br[u] = *(const float4*)&wsel[col >> 6][(size_t)(k0 + kk) * NH + (col & 63)];
            }
        }
        #pragma unroll
        for (int kk = 0; kk < PBK; kk++) {
            float a[8], b[12];
            *(float4*)&a[0] = *(float4*)&sA[cur][kk][tr * 8];
            *(float4*)&a[4] = *(float4*)&sA[cur][kk][tr * 8 + 4];
            *(float4*)&b[0] = *(float4*)&sB[cur][kk][tc * 12];
            *(float4*)&b[4] = *(float4*)&sB[cur][kk][tc * 12 + 4];
            *(float4*)&b[8] = *(float4*)&sB[cur][kk][tc * 12 + 8];
            #pragma unroll
            for (int i = 0; i < 8; i++)
                #pragma unroll
                for (int j = 0; j < 12; j++)
                    acc[i][j] = fmaf(a[i], b[j], acc[i][j]);
        }
        if (ks + 1 < NSTEP) {
            int nxt = cur ^ 1;
            #pragma unroll
            for (int u = 0; u < 2; u++) {
                int f = tid * 2 + u;
                int r = f >> 2, c4 = f & 3;
                sA[nxt][c4 * 4 + 0][r] = ar[u].x;
                sA[nxt][c4 * 4 + 1][r] = ar[u].y;
                sA[nxt][c4 * 4 + 2][r] = ar[u].z;
                sA[nxt][c4 * 4 + 3][r] = ar[u].w;
            }
            #pragma unroll
            for (int u = 0; u < 3; u++) {
                int f  = tid * 3 + u;
                int kk = f / 48, c4 = f % 48;
                *(float4*)&sB[nxt][kk][c4 * 4] = br[u];
            }
        }
        __syncthreads();
    }

    #pragma unroll
    for (int i = 0; i < 8; i++) {
        int r = m0 + tr * 8 + i;
        #pragma unroll
        for (int g = 0; g < 3; g++) {
            int col = tc * 12 + g * 4;
            float* dst = dsel[col >> 6];
            float4 t = make_float4(acc[i][g*4+0], acc[i][g*4+1],
                                   acc[i][g*4+2], acc[i][g*4+3]);
            *(float4*)&dst[(size_t)r * NH + (col & 63)] = t;
        }
    }
}

// ---------------------------------------------------------------------------
// Work items: query tile it (128 rows) split into np = ceil((2it+2)/8)
// near-equal KV pieces. 40 items per batch, LPT order.
// ---------------------------------------------------------------------------
__device__ __forceinline__ void decode_item(int e, int& b, int& it,
                                            int& piece, int& kv0, int& kv1)
{
    b = e / 40;
    int r = e - b * 40;
    int np;
    if (r < 4)       { it = r;               piece = 0;           np = 1; }
    else if (r < 12) { int j = r - 4;  it = 4  + (j >> 1); piece = j & 1;  np = 2; }
    else if (r < 24) { int j = r - 12; it = 8  + j / 3;    piece = j % 3;  np = 3; }
    else             { int j = r - 24; it = 12 + (j >> 2); piece = j & 3;  np = 4; }
    int S    = 2 * it + 2;
    int base = S / np;
    int rem  = S - base * np;
    kv0 = piece * base + min(piece, rem);
    kv1 = kv0 + base + (piece < rem ? 1 : 0);
}

__global__ void init_kernel()
{
    int e = blockIdx.x * 256 + threadIdx.x;
    if (e == 0) g_counter = 0;
    if (e >= NITEMS) return;

    int b, it, piece, kv0, kv1;
    decode_item(e, b, it, piece, kv0, kv1);
    int sz = kv1 - kv0;

    int rank = 0;
    for (int f = 0; f < NITEMS; f++) {
        int fb, fit, fp, fk0, fk1;
        decode_item(f, fb, fit, fp, fk0, fk1);
        int fsz = fk1 - fk0;
        rank += (fsz > sz) || (fsz == sz && f < e);
    }
    g_items[rank * 4 + 0] = b * NQT + it;
    g_items[rank * 4 + 1] = kv0;
    g_items[rank * 4 + 2] = kv1;
    g_items[rank * 4 + 3] = piece;
}

// ---------------------------------------------------------------------------
// Persistent causal flash attention, 128x64 steps, 8x4 thread tile.
// ---------------------------------------------------------------------------
#define QP 132     // pitch for qT / sT (128 rows + 4)
#define KP 68      // pitch for kT / v

struct AttnSmem {
    float qT[64][QP];        // qT[h][row 0..127], pre-scaled
    float kT[2][64][KP];     // kT[h][col 0..63]
    float v [2][64][KP];     // v[token][h]
    float sT[64][QP];        // P transposed: sT[col][row]
    int   slot;
};

extern __shared__ char attn_smem_raw[];

__device__ __forceinline__ void attn_item(
    AttnSmem* sm, int b, int it, int piece, int kv0, int kv1,
    int tid, int ty, int tx)
{
    const float* Qb = g_q + (size_t)b * NT * NH;
    const float* Kb = g_k + (size_t)b * NT * NH;
    const float* Vb = g_v + (size_t)b * NT * NH;
    const int q0 = it * 128;

    // ---- load Q tile (128x64) transposed, pre-scaled ----
    #pragma unroll
    for (int u = 0; u < 8; u++) {
        int f  = u * 256 + tid;
        int rr = f >> 4;
        int c4 = f & 15;
        float4 t = *(const float4*)&Qb[(size_t)(q0 + rr) * NH + c4 * 4];
        sm->qT[c4 * 4 + 0][rr] = t.x * QSCALE;
        sm->qT[c4 * 4 + 1][rr] = t.y * QSCALE;
        sm->qT[c4 * 4 + 2][rr] = t.z * QSCALE;
        sm->qT[c4 * 4 + 3][rr] = t.w * QSCALE;
    }
    // ---- first KV tile into buffer 0 ----
    #pragma unroll
    for (int u = 0; u < 4; u++) {
        int f  = tid * 4 + u;
        int r  = f >> 4;
        int c4 = f & 15;
        size_t gb = (size_t)(kv0 * 64 + r) * NH + c4 * 4;
        float4 tk = *(const float4*)&Kb[gb];
        float4 tv = *(const float4*)&Vb[gb];
        sm->kT[0][c4 * 4 + 0][r] = tk.x;
        sm->kT[0][c4 * 4 + 1][r] = tk.y;
        sm->kT[0][c4 * 4 + 2][r] = tk.z;
        sm->kT[0][c4 * 4 + 3][r] = tk.w;
        *(float4*)&sm->v[0][r][c4 * 4] = tv;
    }
    __syncthreads();

    float o[8][4];
    float m[8], l[8];
    #pragma unroll
    for (int i = 0; i < 8; i++) {
        m[i] = -INFINITY; l[i] = 0.f;
        #pragma unroll
        for (int j = 0; j < 4; j++) o[i][j] = 0.f;
    }

    for (int jt = kv0; jt < kv1; jt++) {
        int cur = (jt - kv0) & 1;
        float4 kr[4], vr[4];
        if (jt + 1 < kv1) {
            #pragma unroll
            for (int u = 0; u < 4; u++) {
                int f  = tid * 4 + u;
                int r  = f >> 4;
                int c4 = f & 15;
                size_t gb = (size_t)((jt + 1) * 64 + r) * NH + c4 * 4;
                kr[u] = *(const float4*)&Kb[gb];
                vr[u] = *(const float4*)&Vb[gb];
            }
        }

        // ---- S = Q @ K^T : 8x4 per thread ----
        float acc[8][4];
        #pragma unroll
        for (int i = 0; i < 8; i++)
            #pragma unroll
            for (int j = 0; j < 4; j++) acc[i][j] = 0.f;
        #pragma unroll
        for (int kk = 0; kk < 64; kk++) {
            float a[8], bv[4];
            *(float4*)&a[0] = *(float4*)&sm->qT[kk][ty * 8];
            *(float4*)&a[4] = *(float4*)&sm->qT[kk][ty * 8 + 4];
            *(float4*)&bv[0] = *(float4*)&sm->kT[cur][kk][tx * 4];
            #pragma unroll
            for (int i = 0; i < 8; i++)
                #pragma unroll
                for (int j = 0; j < 4; j++)
                    acc[i][j] = fmaf(a[i], bv[j], acc[i][j]);
        }

        // ---- causal mask (only when this KV step overlaps the diagonal) ----
        int koff = jt * 64 - q0;        // key_local_base - row_local_base
        if (koff >= 0) {
            #pragma unroll
            for (int i = 0; i < 8; i++) {
                int rr = ty * 8 + i;
                #pragma unroll
                for (int j = 0; j < 4; j++)
                    if (koff + tx * 4 + j > rr) acc[i][j] = -INFINITY;
            }
        }

        // ---- online softmax (16-lane row reductions) ----
        float pr[8][4];
        #pragma unroll
        for (int i = 0; i < 8; i++) {
            float v = fmaxf(fmaxf(acc[i][0], acc[i][1]),
                            fmaxf(acc[i][2], acc[i][3]));
            #pragma unroll
            for (int d = 1; d < 16; d <<= 1)
                v = fmaxf(v, __shfl_xor_sync(0xffffffffu, v, d));
            float mn = fmaxf(m[i], v);
            float alpha = __expf(m[i] - mn);
            m[i] = mn;
            float rs = 0.f;
            #pragma unroll
            for (int j = 0; j < 4; j++) {
                pr[i][j] = __expf(acc[i][j] - mn);
                rs += pr[i][j];
            }
            #pragma unroll
            for (int d = 1; d < 16; d <<= 1)
                rs += __shfl_xor_sync(0xffffffffu, rs, d);
            l[i] = l[i] * alpha + rs;
            #pragma unroll
            for (int j = 0; j < 4; j++) o[i][j] *= alpha;
        }

        // ---- stage P transposed (half-warp local: same ty group) ----
        #pragma unroll
        for (int j = 0; j < 4; j++) {
            *(float4*)&sm->sT[tx * 4 + j][ty * 8] =
                make_float4(pr[0][j], pr[1][j], pr[2][j], pr[3][j]);
            *(float4*)&sm->sT[tx * 4 + j][ty * 8 + 4] =
                make_float4(pr[4][j], pr[5][j], pr[6][j], pr[7][j]);
        }
        __syncwarp();

        // ---- O += P @ V ----
        #pragma unroll
        for (int kk = 0; kk < 64; kk++) {
            float p[8], vv[4];
            *(float4*)&p[0] = *(float4*)&sm->sT[kk][ty * 8];
            *(float4*)&p[4] = *(float4*)&sm->sT[kk][ty * 8 + 4];
            *(float4*)&vv[0] = *(float4*)&sm->v[cur][kk][tx * 4];
            #pragma unroll
            for (int i = 0; i < 8; i++)
                #pragma unroll
                for (int j = 0; j < 4; j++)
                    o[i][j] = fmaf(p[i], vv[j], o[i][j]);
        }

        // ---- store prefetched KV into other buffer ----
        if (jt + 1 < kv1) {
            int nxt = cur ^ 1;
            #pragma unroll
            for (int u = 0; u < 4; u++) {
                int f  = tid * 4 + u;
                int r  = f >> 4;
                int c4 = f & 15;
                sm->kT[nxt][c4 * 4 + 0][r] = kr[u].x;
                sm->kT[nxt][c4 * 4 + 1][r] = kr[u].y;
                sm->kT[nxt][c4 * 4 + 2][r] = kr[u].z;
                sm->kT[nxt][c4 * 4 + 3][r] = kr[u].w;
                *(float4*)&sm->v[nxt][r][c4 * 4] = vr[u];
            }
        }
        __syncthreads();
    }

    // ---- write unnormalized partials ----
    const int slot = (b * NQT + it) * 4 + piece;
    float* po = g_po + (size_t)slot * 128 * NH;
    #pragma unroll
    for (int i = 0; i < 8; i++) {
        int rr = ty * 8 + i;
        if (tx == 0) {
            g_pm[slot * 128 + rr] = m[i];
            g_pl[slot * 128 + rr] = l[i];
        }
        *(float4*)&po[(size_t)rr * NH + tx * 4] =
            make_float4(o[i][0], o[i][1], o[i][2], o[i][3]);
    }
}

__global__ __launch_bounds__(256, 1) void attn_kernel()
{
    AttnSmem* sm = reinterpret_cast<AttnSmem*>(attn_smem_raw);
    const int tid = threadIdx.x;
    const int ty  = tid >> 4;
    const int tx  = tid & 15;

    for (;;) {
        if (tid == 0) sm->slot = atomicAdd(&g_counter, 1);
        __syncthreads();
        int slot = sm->slot;
        __syncthreads();
        if (slot >= NITEMS) return;

        int w0    = g_items[slot * 4 + 0];
        int kv0   = g_items[slot * 4 + 1];
        int kv1   = g_items[slot * 4 + 2];
        int piece = g_items[slot * 4 + 3];

        attn_item(sm, w0 / NQT, w0 % NQT, piece, kv0, kv1, tid, ty, tx);
        __syncthreads();
    }
}

// ---------------------------------------------------------------------------
// Merge partials -> output. One thread per query row; running log-sum-exp.
// ---------------------------------------------------------------------------
__global__ void merge_kernel(float* __restrict__ out)
{
    int row = blockIdx.x * 256 + threadIdx.x;   // 0 .. NB*NT-1
    if (row >= NB * NT) return;
    int b  = row >> 11;
    int t  = row & (NT - 1);
    int it = t >> 7;
    int rr = t & 127;

    int np = (2 * it + 9) / 8;    // ceil((2it+2)/8)
    int slot0 = (b * NQT + it) * 4;

    float M = -INFINITY, L = 0.f;
    float4 acc[16];
    #pragma unroll
    for (int c = 0; c < 16; c++) acc[c] = make_float4(0.f, 0.f, 0.f, 0.f);

    for (int p = 0; p < np; p++) {
        int slot = slot0 + p;
        float mp = g_pm[slot * 128 + rr];
        float lp = g_pl[slot * 128 + rr];
        float Mn = fmaxf(M, mp);
        float a0 = __expf(M - Mn);
        float a1 = __expf(mp - Mn);
        L = L * a0 + lp * a1;
        const float* po = g_po + (size_t)slot * 128 * NH + (size_t)rr * NH;
        #pragma unroll
        for (int c = 0; c < 16; c++) {
            float4 v = *(const float4*)&po[c * 4];
            acc[c].x = acc[c].x * a0 + v.x * a1;
            acc[c].y = acc[c].y * a0 + v.y * a1;
            acc[c].z = acc[c].z * a0 + v.z * a1;
            acc[c].w = acc[c].w * a0 + v.w * a1;
        }
        M = Mn;
    }
    float inv = 1.f / L;
    #pragma unroll
    for (int c = 0; c < 16; c++) {
        *(float4*)&out[(size_t)row * NH + c * 4] =
            make_float4(acc[c].x * inv, acc[c].y * inv,
                        acc[c].z * inv, acc[c].w * inv);
    }
}

// ---------------------------------------------------------------------------

extern "C" void kernel_launch(void* const* d_in, const int* in_sizes, int n_in,
                              void* d_out, int out_size)
{
    const float* x  = (const float*)d_in[0];
    const float* wq = (const float*)d_in[1];
    const float* wk = (const float*)d_in[2];
    const float* wv = (const float*)d_in[3];
    float* out = (float*)d_out;

    const int attn_smem = (int)sizeof(AttnSmem);
    cudaFuncSetAttribute(attn_kernel,
                         cudaFuncAttributeMaxDynamicSharedMemorySize,
                         attn_smem);

    proj_kernel<<<dim3((NB * NT) / 128), 256>>>(x, wq, wk, wv);
    init_kernel<<<(NITEMS + 255) / 256, 256>>>();
    attn_kernel<<<148, 256, attn_smem>>>();
    merge_kernel<<<(NB * NT + 255) / 256, 256>>>(out);
}

// round 13
// speedup vs baseline: 1.2856x; 1.2856x over previous
#include <cuda_runtime.h>
#include <math.h>
#include <stdint.h>

#define NB 8
#define NT 2048
#define NC 1024
#define NH 64
#define QSCALE 0.125f    // 64^-0.5
#define NTILES (NT / 64) // 32

// Scratch for projections.
__device__ float g_q[NB * NT * NH];
__device__ float g_k[NB * NT * NH];
__device__ float g_v[NB * NT * NH];

// ============================================================================
// Packed f32x2 helpers (family-level PTX, sm_100+).
// ============================================================================
__device__ __forceinline__ void fma2(uint64_t& d, uint64_t a, uint64_t b) {
    asm("fma.rn.f32x2 %0, %1, %2, %0;" : "+l"(d) : "l"(a), "l"(b));
}
__device__ __forceinline__ void mul2(uint64_t& d, uint64_t a) {
    asm("mul.rn.f32x2 %0, %0, %1;" : "+l"(d) : "l"(a));
}
__device__ __forceinline__ uint64_t pack2(float x, float y) {
    uint64_t r;
    asm("mov.b64 %0, {%1, %2};" : "=l"(r)
        : "r"(__float_as_uint(x)), "r"(__float_as_uint(y)));
    return r;
}
__device__ __forceinline__ uint64_t dup2(float x) { return pack2(x, x); }
__device__ __forceinline__ float2 unpack2(uint64_t p) {
    uint32_t lo, hi;
    asm("mov.b64 {%0, %1}, %2;" : "=r"(lo), "=r"(hi) : "l"(p));
    return make_float2(__uint_as_float(lo), __uint_as_float(hi));
}
// Reinterpret a float4 (4 consecutive regs) as two 64-bit lane pairs.
__device__ __forceinline__ void f4_pairs(const float4& v, uint64_t& p0, uint64_t& p1) {
    p0 = pack2(v.x, v.y);
    p1 = pack2(v.z, v.w);
}

// ---------------------------------------------------------------------------
// Fused projection GEMM: {q,k,v} = x @ {wq,wk,wv}  — FFMA2 inner loop.
// M = 16384, K = 1024, N = 192. Block tile 128x192, thread tile 8x12.
// ---------------------------------------------------------------------------
#define PBK 16
#define PAP 132
#define PBP 196

__global__ __launch_bounds__(256) void proj_kernel(
    const float* __restrict__ x,
    const float* __restrict__ wq,
    const float* __restrict__ wk,
    const float* __restrict__ wv)
{
    __shared__ float sA[2][PBK][PAP];
    __shared__ float sB[2][PBK][PBP];

    const int m0  = blockIdx.x * 128;
    const int tid = threadIdx.x;
    const int tr  = tid >> 4;
    const int tc  = tid & 15;

    const float* wsel[3] = {wq, wk, wv};
    float*       dsel[3] = {g_q, g_k, g_v};

    uint64_t acc2[8][6];   // [row][col-pair], lanes (col 2jp, 2jp+1)
    #pragma unroll
    for (int i = 0; i < 8; i++)
        #pragma unroll
        for (int j = 0; j < 6; j++) acc2[i][j] = 0ull;

    float4 ar[2], br[3];
    #pragma unroll
    for (int u = 0; u < 2; u++) {
        int f = tid * 2 + u;
        int r = f >> 2, c4 = f & 3;
        ar[u] = *(const float4*)&x[(size_t)(m0 + r) * NC + c4 * 4];
    }
    #pragma unroll
    for (int u = 0; u < 3; u++) {
        int f  = tid * 3 + u;
        int kk = f / 48, c4 = f % 48;
        int col = c4 * 4;
        br[u] = *(const float4*)&wsel[col >> 6][(size_t)kk * NH + (col & 63)];
    }
    #pragma unroll
    for (int u = 0; u < 2; u++) {
        int f = tid * 2 + u;
        int r = f >> 2, c4 = f & 3;
        sA[0][c4 * 4 + 0][r] = ar[u].x;
        sA[0][c4 * 4 + 1][r] = ar[u].y;
        sA[0][c4 * 4 + 2][r] = ar[u].z;
        sA[0][c4 * 4 + 3][r] = ar[u].w;
    }
    #pragma unroll
    for (int u = 0; u < 3; u++) {
        int f  = tid * 3 + u;
        int kk = f / 48, c4 = f % 48;
        *(float4*)&sB[0][kk][c4 * 4] = br[u];
    }
    __syncthreads();

    const int NSTEP = NC / PBK;
    for (int ks = 0; ks < NSTEP; ks++) {
        int cur = ks & 1;
        if (ks + 1 < NSTEP) {
            int k0 = (ks + 1) * PBK;
            #pragma unroll
            for (int u = 0; u < 2; u++) {
                int f = tid * 2 + u;
                int r = f >> 2, c4 = f & 3;
                ar[u] = *(const float4*)&x[(size_t)(m0 + r) * NC + k0 + c4 * 4];
            }
            #pragma unroll
            for (int u = 0; u < 3; u++) {
                int f  = tid * 3 + u;
                int kk = f / 48, c4 = f % 48;
                int col = c4 * 4;
                br[u] = *(const float4*)&wsel[col >> 6][(size_t)(k0 + kk) * NH + (col & 63)];
            }
        }
        #pragma unroll
        for (int kk = 0; kk < PBK; kk++) {
            float a[8];
            float4 b0, b1, b2;
            *(float4*)&a[0] = *(float4*)&sA[cur][kk][tr * 8];
            *(float4*)&a[4] = *(float4*)&sA[cur][kk][tr * 8 + 4];
            b0 = *(float4*)&sB[cur][kk][tc * 12];
            b1 = *(float4*)&sB[cur][kk][tc * 12 + 4];
            b2 = *(float4*)&sB[cur][kk][tc * 12 + 8];
            uint64_t bP[6];
            f4_pairs(b0, bP[0], bP[1]);
            f4_pairs(b1, bP[2], bP[3]);
            f4_pairs(b2, bP[4], bP[5]);
            #pragma unroll
            for (int i = 0; i < 8; i++) {
                uint64_t aD = dup2(a[i]);
                #pragma unroll
                for (int j = 0; j < 6; j++)
                    fma2(acc2[i][j], aD, bP[j]);
            }
        }
        if (ks + 1 < NSTEP) {
            int nxt = cur ^ 1;
            #pragma unroll
            for (int u = 0; u < 2; u++) {
                int f = tid * 2 + u;
                int r = f >> 2, c4 = f & 3;
                sA[nxt][c4 * 4 + 0][r] = ar[u].x;
                sA[nxt][c4 * 4 + 1][r] = ar[u].y;
                sA[nxt][c4 * 4 + 2][r] = ar[u].z;
                sA[nxt][c4 * 4 + 3][r] = ar[u].w;
            }
            #pragma unroll
            for (int u = 0; u < 3; u++) {
                int f  = tid * 3 + u;
                int kk = f / 48, c4 = f % 48;
                *(float4*)&sB[nxt][kk][c4 * 4] = br[u];
            }
        }
        __syncthreads();
    }

    #pragma unroll
    for (int i = 0; i < 8; i++) {
        int r = m0 + tr * 8 + i;
        #pragma unroll
        for (int g = 0; g < 3; g++) {
            int col = tc * 12 + g * 4;
            float* dst = dsel[col >> 6];
            float2 t0 = unpack2(acc2[i][2 * g]);
            float2 t1 = unpack2(acc2[i][2 * g + 1]);
            *(float4*)&dst[(size_t)r * NH + (col & 63)] =
                make_float4(t0.x, t0.y, t1.x, t1.y);
        }
    }
}

// ---------------------------------------------------------------------------
// Causal flash attention v6: R4 geometry (pair p / 31-p, double-buffered KV,
// 1 barrier/step) + FFMA2 row-pair inner loops (pairs from registers only).
// grid = (16, 8), 256 threads.
// ---------------------------------------------------------------------------
#define PITCH 68
struct AttnSmem {
    float qT[64][PITCH];     // qT[h][row], pre-scaled
    float kT[2][64][PITCH];  // kT[h][col]
    float v [2][64][PITCH];  // v[token][h]
    float sT[64][PITCH];     // P transposed: sT[col][row]
};

extern __shared__ char attn_smem_raw[];

__device__ __forceinline__ void attn_tile(
    AttnSmem* sm, const float* Qb, const float* Kb, const float* Vb,
    float* out, int b, int it, int tid, int ty, int tx)
{
    // ---- load Q tile transposed, pre-scaled ----
    #pragma unroll
    for (int u = 0; u < 4; u++) {
        int f  = tid * 4 + u;
        int r  = f >> 4;
        int c4 = f & 15;
        float4 t = *(const float4*)&Qb[(size_t)(it * 64 + r) * NH + c4 * 4];
        sm->qT[c4 * 4 + 0][r] = t.x * QSCALE;
        sm->qT[c4 * 4 + 1][r] = t.y * QSCALE;
        sm->qT[c4 * 4 + 2][r] = t.z * QSCALE;
        sm->qT[c4 * 4 + 3][r] = t.w * QSCALE;
    }
    // ---- KV tile 0 into buffer 0 ----
    #pragma unroll
    for (int u = 0; u < 4; u++) {
        int f  = tid * 4 + u;
        int r  = f >> 4;
        int c4 = f & 15;
        size_t gb = (size_t)r * NH + c4 * 4;
        float4 tk = *(const float4*)&Kb[gb];
        float4 tv = *(const float4*)&Vb[gb];
        sm->kT[0][c4 * 4 + 0][r] = tk.x;
        sm->kT[0][c4 * 4 + 1][r] = tk.y;
        sm->kT[0][c4 * 4 + 2][r] = tk.z;
        sm->kT[0][c4 * 4 + 3][r] = tk.w;
        *(float4*)&sm->v[0][r][c4 * 4] = tv;
    }
    __syncthreads();

    uint64_t o2[2][4];       // [row-pair][col], lanes (row 2p, 2p+1)
    float m[4], l[4];
    #pragma unroll
    for (int p = 0; p < 2; p++)
        #pragma unroll
        for (int j = 0; j < 4; j++) o2[p][j] = 0ull;
    #pragma unroll
    for (int i = 0; i < 4; i++) { m[i] = -INFINITY; l[i] = 0.f; }

    for (int jt = 0; jt <= it; jt++) {
        int cur = jt & 1;
        float4 kr[4], vr[4];
        if (jt < it) {
            #pragma unroll
            for (int u = 0; u < 4; u++) {
                int f  = tid * 4 + u;
                int r  = f >> 4;
                int c4 = f & 15;
                size_t gb = (size_t)((jt + 1) * 64 + r) * NH + c4 * 4;
                kr[u] = *(const float4*)&Kb[gb];
                vr[u] = *(const float4*)&Vb[gb];
            }
        }

        // ---- S = Q @ K^T : row-pair FFMA2 ----
        uint64_t acc2[2][4];
        #pragma unroll
        for (int p = 0; p < 2; p++)
            #pragma unroll
            for (int j = 0; j < 4; j++) acc2[p][j] = 0ull;
        #pragma unroll
        for (int kk = 0; kk < 64; kk++) {
            float4 q4 = *(float4*)&sm->qT[kk][ty * 4];
            float4 k4 = *(float4*)&sm->kT[cur][kk][tx * 4];
            uint64_t aP[2];
            f4_pairs(q4, aP[0], aP[1]);          // row pairs (free)
            uint64_t kD[4] = {dup2(k4.x), dup2(k4.y), dup2(k4.z), dup2(k4.w)};
            #pragma unroll
            for (int p = 0; p < 2; p++)
                #pragma unroll
                for (int j = 0; j < 4; j++)
                    fma2(acc2[p][j], aP[p], kD[j]);
        }

        // ---- unpack, mask, softmax (scalar, as proven R3 code) ----
        float acc[4][4];
        #pragma unroll
        for (int p = 0; p < 2; p++)
            #pragma unroll
            for (int j = 0; j < 4; j++) {
                float2 t = unpack2(acc2[p][j]);
                acc[2 * p    ][j] = t.x;
                acc[2 * p + 1][j] = t.y;
            }

        if (jt == it) {
            #pragma unroll
            for (int i = 0; i < 4; i++) {
                int qi = ty * 4 + i;
                #pragma unroll
                for (int j = 0; j < 4; j++)
                    if (tx * 4 + j > qi) acc[i][j] = -INFINITY;
            }
        }

        float alpha[4], pr[4][4];
        #pragma unroll
        for (int i = 0; i < 4; i++) {
            float v = fmaxf(fmaxf(acc[i][0], acc[i][1]),
                            fmaxf(acc[i][2], acc[i][3]));
            #pragma unroll
            for (int d = 1; d < 16; d <<= 1)
                v = fmaxf(v, __shfl_xor_sync(0xffffffffu, v, d));
            float mn = fmaxf(m[i], v);
            alpha[i] = __expf(m[i] - mn);
            m[i] = mn;
            float rs = 0.f;
            #pragma unroll
            for (int j = 0; j < 4; j++) {
                pr[i][j] = __expf(acc[i][j] - mn);
                rs += pr[i][j];
            }
            #pragma unroll
            for (int d = 1; d < 16; d <<= 1)
                rs += __shfl_xor_sync(0xffffffffu, rs, d);
            l[i] = l[i] * alpha[i] + rs;
        }
        // O *= alpha (packed row pairs)
        uint64_t alphaP[2] = {pack2(alpha[0], alpha[1]), pack2(alpha[2], alpha[3])};
        #pragma unroll
        for (int p = 0; p < 2; p++)
            #pragma unroll
            for (int j = 0; j < 4; j++) mul2(o2[p][j], alphaP[p]);

        // ---- stage P transposed (half-warp local) ----
        #pragma unroll
        for (int j = 0; j < 4; j++)
            *(float4*)&sm->sT[tx * 4 + j][ty * 4] =
                make_float4(pr[0][j], pr[1][j], pr[2][j], pr[3][j]);
        __syncwarp();

        // ---- O += P @ V : row-pair FFMA2 (p-pairs free from sT) ----
        #pragma unroll
        for (int kk = 0; kk < 64; kk++) {
            float4 p4 = *(float4*)&sm->sT[kk][ty * 4];
            float4 v4 = *(float4*)&sm->v[cur][kk][tx * 4];
            uint64_t pP[2];
            f4_pairs(p4, pP[0], pP[1]);
            uint64_t vD[4] = {dup2(v4.x), dup2(v4.y), dup2(v4.z), dup2(v4.w)};
            #pragma unroll
            for (int p = 0; p < 2; p++)
                #pragma unroll
                for (int j = 0; j < 4; j++)
                    fma2(o2[p][j], pP[p], vD[j]);
        }

        if (jt < it) {
            int nxt = cur ^ 1;
            #pragma unroll
            for (int u = 0; u < 4; u++) {
                int f  = tid * 4 + u;
                int r  = f >> 4;
                int c4 = f & 15;
                sm->kT[nxt][c4 * 4 + 0][r] = kr[u].x;
                sm->kT[nxt][c4 * 4 + 1][r] = kr[u].y;
                sm->kT[nxt][c4 * 4 + 2][r] = kr[u].z;
                sm->kT[nxt][c4 * 4 + 3][r] = kr[u].w;
                *(float4*)&sm->v[nxt][r][c4 * 4] = vr[u];
            }
        }
        __syncthreads();
    }

    // ---- normalize and write (unpack row pairs) ----
    #pragma unroll
    for (int p = 0; p < 2; p++) {
        float2 c0 = unpack2(o2[p][0]);
        float2 c1 = unpack2(o2[p][1]);
        float2 c2 = unpack2(o2[p][2]);
        float2 c3 = unpack2(o2[p][3]);
        float inv0 = 1.f / l[2 * p];
        float inv1 = 1.f / l[2 * p + 1];
        size_t r0 = (size_t)b * NT + it * 64 + ty * 4 + 2 * p;
        *(float4*)&out[r0 * NH + tx * 4] =
            make_float4(c0.x * inv0, c1.x * inv0, c2.x * inv0, c3.x * inv0);
        *(float4*)&out[(r0 + 1) * NH + tx * 4] =
            make_float4(c0.y * inv1, c1.y * inv1, c2.y * inv1, c3.y * inv1);
    }
}

__global__ __launch_bounds__(256) void attn_kernel(float* __restrict__ out)
{
    AttnSmem* sm = reinterpret_cast<AttnSmem*>(attn_smem_raw);

    const int b   = blockIdx.y;
    const int p   = blockIdx.x;
    const int tid = threadIdx.x;
    const int ty  = tid >> 4;
    const int tx  = tid & 15;

    const float* Qb = g_q + (size_t)b * NT * NH;
    const float* Kb = g_k + (size_t)b * NT * NH;
    const float* Vb = g_v + (size_t)b * NT * NH;

    attn_tile(sm, Qb, Kb, Vb, out, b, NTILES - 1 - p, tid, ty, tx);
    __syncthreads();
    attn_tile(sm, Qb, Kb, Vb, out, b, p, tid, ty, tx);
}

// ---------------------------------------------------------------------------

extern "C" void kernel_launch(void* const* d_in, const int* in_sizes, int n_in,
                              void* d_out, int out_size)
{
    const float* x  = (const float*)d_in[0];
    const float* wq = (const float*)d_in[1];
    const float* wk = (const float*)d_in[2];
    const float* wv = (const float*)d_in[3];
    float* out = (float*)d_out;

    const int attn_smem = (int)sizeof(AttnSmem);
    cudaFuncSetAttribute(attn_kernel,
                         cudaFuncAttributeMaxDynamicSharedMemorySize,
                         attn_smem);

    proj_kernel<<<dim3((NB * NT) / 128), 256>>>(x, wq, wk, wv);
    attn_kernel<<<dim3(NTILES / 2, NB), 256, attn_smem>>>(out);
}